// round 14
// baseline (speedup 1.0000x reference)
#include <cuda_runtime.h>
#include <cstdint>

#define KC     9
#define TPB    256
#define TROWS  512                   // rows per pipeline stage
#define STAGE_F4 (TROWS * KC / 4)    // 1152 float4 per stage
#define NT     4                     // tiles per block
#define BLK_ROWS (TROWS * NT)        // 2048 rows per block

#define LOG2E 1.4426950408889634f
#define LN2_OVER_LN9 0.31546487678572877f   // ln2/ln9

__device__ float        g_partials[65536];
__device__ unsigned int g_counter = 0;

__device__ __forceinline__ float warp_reduce(float v) {
#pragma unroll
    for (int o = 16; o; o >>= 1) v += __shfl_xor_sync(0xffffffffu, v, o);
    return v;
}
__device__ __forceinline__ float ex2(float x) {
    float r; asm("ex2.approx.f32 %0, %1;" : "=f"(r) : "f"(x)); return r;
}
__device__ __forceinline__ float lg2(float x) {
    float r; asm("lg2.approx.f32 %0, %1;" : "=f"(r) : "f"(x)); return r;
}
__device__ __forceinline__ void cp_async16(unsigned int saddr, const void* gptr) {
    asm volatile("cp.async.cg.shared.global [%0], [%1], 16;" :: "r"(saddr), "l"(gptr));
}

__global__ void __launch_bounds__(TPB)
ordinal_loss_fused(const float* __restrict__ logits,
                   const int*   __restrict__ y,
                   float*       __restrict__ out,
                   int B, int nblocks) {
    __shared__ __align__(16) float sbuf[2][TROWS * KC];  // 2 x 18432 B
    __shared__ float tw[KC * KC];
    __shared__ float ws[TPB / 32];
    __shared__ bool  s_last;

    // tail-weight table (|k-y|-1)^3
    if (threadIdx.x < KC * KC) {
        const int yy = threadIdx.x / KC;
        const int k  = threadIdx.x - yy * KC;
        const int ad = (k > yy) ? (k - yy) : (yy - k);
        const float f1 = (ad > 1) ? (float)(ad - 1) : 0.0f;
        tw[threadIdx.x] = f1 * f1 * f1;
    }

    const long long brow = (long long)blockIdx.x * BLK_ROWS;

    // prefetch tile t into buffer buf (async for full tiles, sync loads for partial)
    auto prefetch = [&](int t, int buf) {
        const long long r0 = brow + (long long)t * TROWS;
        const long long rem = (long long)B - r0;
        if (rem >= TROWS) {
            const float* src = logits + r0 * KC;
            for (int j = threadIdx.x; j < STAGE_F4; j += TPB) {
                unsigned int dst =
                    (unsigned int)__cvta_generic_to_shared(&sbuf[buf][j * 4]);
                cp_async16(dst, src + (size_t)j * 4);
            }
        } else if (rem > 0) {
            const int n = (int)rem * KC;
            const float* src = logits + r0 * KC;
            for (int j = threadIdx.x; j < n; j += TPB) sbuf[buf][j] = src[j];
        }
        asm volatile("cp.async.commit_group;");
    };

    float contrib = 0.0f;

    prefetch(0, 0);
#pragma unroll
    for (int t = 0; t < NT; t++) {
        if (t + 1 < NT) {
            prefetch(t + 1, (t + 1) & 1);
            asm volatile("cp.async.wait_group 1;");
        } else {
            asm volatile("cp.async.wait_group 0;");
        }
        __syncthreads();                     // tile t data visible to all threads

        const float* sl = sbuf[t & 1];
        const long long r0 = brow + (long long)t * TROWS;
        const int nrows = (int)min((long long)TROWS, max((long long)B - r0, 0LL));

#pragma unroll
        for (int s = 0; s < TROWS / TPB; s++) {
            const int r = threadIdx.x + s * TPB;     // stride-9 smem: conflict-free
            if (r < nrows) {
                const int   yy   = y[r0 + r];
                const int   base = r * KC;
                const float yf   = (float)yy;

                // exp pass: scale by log2e at use, bare EX2, running cdf
                float e[KC], cdf[KC];
                float run = 0.0f;
#pragma unroll
                for (int k = 0; k < KC; k++) {
                    e[k] = ex2(sl[base + k] * LOG2E);
                    run += e[k];
                    cdf[k] = run;
                }
                const float Z  = run;
                const float rZ = __fdividef(1.0f, Z);

                // target / neighbor probs via dynamic smem loads
                const float ly   = sl[base + yy] * LOG2E;
                const float py_e = ex2(ly);
                const float pl_e = (yy > 0)      ? ex2(sl[base + yy - 1] * LOG2E) : 0.0f;
                const float pr_e = (yy < KC - 1) ? ex2(sl[base + yy + 1] * LOG2E) : 0.0f;

                const float nll_lg2 = lg2(Z) - ly;   // nll / ln2

                const float* twr = &tw[yy * KC];
                float far_e = 0.0f, tail_e = 0.0f, emd_z = 0.0f;
#pragma unroll
                for (int k = 0; k < KC; k++) {
                    const float twk = twr[k];        // LDS.32, conflict-free
                    tail_e = fmaf(e[k], twk, tail_e);
                    far_e  = fmaxf(far_e, e[k] * fminf(twk, 1.0f));

                    const float tt = __saturatef(yf - (float)(k - 1));  // 1{k<=y}
                    const float df = fmaf(-Z, tt, cdf[k]);              // cdf - t*Z
                    const float w  = (k == 0) ? 3.0f/95.0f : (k == 1) ? 7.0f/95.0f
                                   : (k == KC-1) ? 25.0f/95.0f : 10.0f/95.0f;
                    emd_z = fmaf(df * df, w, emd_z);
                }

                const float py   = py_e * rZ;
                const float emd2 = emd_z * rZ * rZ;
                const float far_margin = fmaxf(fmaf(far_e, rZ, 0.15f - py), 0.0f);
                const float local_peak = fmaxf(fmaf(fmaxf(pl_e, pr_e), rZ, 0.35f - py), 0.0f);

                contrib += nll_lg2 * LN2_OVER_LN9
                         + 0.4f * (7.0f * far_margin + 9.0f * (tail_e * rZ)
                                 + 12.0f * local_peak + 1.2f * emd2);
            }
        }
        __syncthreads();                     // done reading before buffer reuse
    }

    // ---- block reduction ----
    contrib = warp_reduce(contrib);
    if ((threadIdx.x & 31) == 0) ws[threadIdx.x >> 5] = contrib;
    __syncthreads();
    if (threadIdx.x < 32) {
        float v = (threadIdx.x < TPB / 32) ? ws[threadIdx.x] : 0.0f;
        v = warp_reduce(v);
        if (threadIdx.x == 0) {
            g_partials[blockIdx.x] = v;
            __threadfence();
            unsigned int tk = atomicAdd(&g_counter, 1u);
            s_last = (tk == (unsigned int)(nblocks - 1));
        }
    }
    __syncthreads();

    // ---- last arriving block: deterministic fixed-order final sum ----
    if (s_last) {
        float v = 0.0f;
        for (int i = threadIdx.x; i < nblocks; i += TPB) v += g_partials[i];
        v = warp_reduce(v);
        if ((threadIdx.x & 31) == 0) ws[threadIdx.x >> 5] = v;
        __syncthreads();
        if (threadIdx.x < 32) {
            float tv = (threadIdx.x < TPB / 32) ? ws[threadIdx.x] : 0.0f;
            tv = warp_reduce(tv);
            if (threadIdx.x == 0) {
                out[0] = tv / (float)B;
                g_counter = 0;               // re-arm for next graph replay
            }
        }
    }
}

extern "C" void kernel_launch(void* const* d_in, const int* in_sizes, int n_in,
                              void* d_out, int out_size) {
    const float* logits = (const float*)d_in[0];
    const int*   y      = (const int*)d_in[1];
    const int    B      = in_sizes[1];

    const int nblocks = (B + BLK_ROWS - 1) / BLK_ROWS;   // 2048 for B = 4,194,304

    ordinal_loss_fused<<<nblocks, TPB>>>(logits, y, (float*)d_out, B, nblocks);
}

// round 16
// speedup vs baseline: 1.0061x; 1.0061x over previous
#include <cuda_runtime.h>

#define KC     9
#define TPB    256
#define QROWS  256                  // rows per phase (1 row/thread/phase)
#define NQ     4
#define TILE   (QROWS * NQ)         // 1024 rows/block
#define QF4    (QROWS * KC / 4)     // 576 float4 per quarter

#define LOG2E 1.4426950408889634f
#define LN2_OVER_LN9 0.31546487678572877f   // ln2/ln9

__device__ float        g_partials[65536];
__device__ unsigned int g_counter = 0;

__device__ __forceinline__ float warp_reduce(float v) {
#pragma unroll
    for (int o = 16; o; o >>= 1) v += __shfl_xor_sync(0xffffffffu, v, o);
    return v;
}
__device__ __forceinline__ float ex2(float x) {
    float r; asm("ex2.approx.f32 %0, %1;" : "=f"(r) : "f"(x)); return r;
}
__device__ __forceinline__ float lg2(float x) {
    float r; asm("lg2.approx.f32 %0, %1;" : "=f"(r) : "f"(x)); return r;
}

__global__ void __launch_bounds__(TPB)
ordinal_loss_fused(const float* __restrict__ logits,
                   const int*   __restrict__ y,
                   float*       __restrict__ out,
                   int B, int nblocks) {
    __shared__ float sl[TILE * KC];          // 36864 B (prescaled logits)
    __shared__ float tw[KC * KC];
    __shared__ float ws[TPB / 32];
    __shared__ bool  s_last;

    // tail-weight table (|k-y|-1)^3
    if (threadIdx.x < KC * KC) {
        const int yy = threadIdx.x / KC;
        const int k  = threadIdx.x - yy * KC;
        const int ad = (k > yy) ? (k - yy) : (yy - k);
        const float f1 = (ad > 1) ? (float)(ad - 1) : 0.0f;
        tw[threadIdx.x] = f1 * f1 * f1;
    }

    const int row0 = blockIdx.x * TILE;
    float contrib = 0.0f;

    // ---- R7-champion per-row body ----
    auto row_compute = [&](int r) -> float {
        const int   yy   = y[row0 + r];
        const int   base = r * KC;
        const float yf   = (float)yy;

        float e[KC], cdf[KC];
        float run = 0.0f;
#pragma unroll
        for (int k = 0; k < KC; k++) {
            e[k] = ex2(sl[base + k]);        // prescaled: bare EX2
            run += e[k];
            cdf[k] = run;
        }
        const float Z  = run;
        const float rZ = __fdividef(1.0f, Z);

        const float ly   = sl[base + yy];
        const float py_e = ex2(ly);
        const float pl_e = (yy > 0)      ? ex2(sl[base + yy - 1]) : 0.0f;
        const float pr_e = (yy < KC - 1) ? ex2(sl[base + yy + 1]) : 0.0f;

        const float nll_lg2 = lg2(Z) - ly;

        const float* twr = &tw[yy * KC];
        float far_e = 0.0f, tail_e = 0.0f, emd_z = 0.0f;
#pragma unroll
        for (int k = 0; k < KC; k++) {
            const float twk = twr[k];
            tail_e = fmaf(e[k], twk, tail_e);
            far_e  = fmaxf(far_e, e[k] * fminf(twk, 1.0f));

            const float t  = __saturatef(yf - (float)(k - 1));
            const float df = fmaf(-Z, t, cdf[k]);
            const float w  = (k == 0) ? 3.0f/95.0f : (k == 1) ? 7.0f/95.0f
                           : (k == KC-1) ? 25.0f/95.0f : 10.0f/95.0f;
            emd_z = fmaf(df * df, w, emd_z);
        }

        const float py   = py_e * rZ;
        const float emd2 = emd_z * rZ * rZ;
        const float far_margin = fmaxf(fmaf(far_e, rZ, 0.15f - py), 0.0f);
        const float local_peak = fmaxf(fmaf(fmaxf(pl_e, pr_e), rZ, 0.35f - py), 0.0f);

        return nll_lg2 * LN2_OVER_LN9
             + 0.4f * (7.0f * far_margin + 9.0f * (tail_e * rZ)
                     + 12.0f * local_peak + 1.2f * emd2);
    };

    if (B - row0 >= TILE) {
        // ======== register-pipelined fast path ========
        const float4* src = reinterpret_cast<const float4*>(logits + (size_t)row0 * KC);
        const int t0 = threadIdx.x, t1 = threadIdx.x + 256, t2 = threadIdx.x + 512;
        const bool has2 = (t2 < QF4);        // tid < 64
        float4* dst = reinterpret_cast<float4*>(sl);

        auto stsq = [&](int q, float4 v0, float4 v1, float4 v2) {
            v0.x *= LOG2E; v0.y *= LOG2E; v0.z *= LOG2E; v0.w *= LOG2E;
            v1.x *= LOG2E; v1.y *= LOG2E; v1.z *= LOG2E; v1.w *= LOG2E;
            dst[q * QF4 + t0] = v0;
            dst[q * QF4 + t1] = v1;
            if (has2) {
                v2.x *= LOG2E; v2.y *= LOG2E; v2.z *= LOG2E; v2.w *= LOG2E;
                dst[q * QF4 + t2] = v2;
            }
        };
        auto ldq = [&](int q, float4& v0, float4& v1, float4& v2) {
            v0 = __ldcs(src + q * QF4 + t0);
            v1 = __ldcs(src + q * QF4 + t1);
            if (has2) v2 = __ldcs(src + q * QF4 + t2);
        };

        float4 a0, a1, a2, b0, b1, b2;

        // prologue: LDG Q0 -> STS Q0 ; LDG Q1 in flight
        ldq(0, a0, a1, a2);
        stsq(0, a0, a1, a2);
        ldq(1, b0, b1, b2);
        __syncthreads();
        // phase 0: compute Q0 | STS Q1 | LDG Q2
        contrib += row_compute(0 * QROWS + threadIdx.x);
        stsq(1, b0, b1, b2);
        ldq(2, a0, a1, a2);
        __syncthreads();
        // phase 1: compute Q1 | STS Q2 | LDG Q3
        contrib += row_compute(1 * QROWS + threadIdx.x);
        stsq(2, a0, a1, a2);
        ldq(3, b0, b1, b2);
        __syncthreads();
        // phase 2: compute Q2 | STS Q3
        contrib += row_compute(2 * QROWS + threadIdx.x);
        stsq(3, b0, b1, b2);
        __syncthreads();
        // phase 3: compute Q3
        contrib += row_compute(3 * QROWS + threadIdx.x);
    } else {
        // ======== partial tail block (correctness path) ========
        const int nrows = B - row0;
        for (int j = threadIdx.x; j < nrows * KC; j += TPB)
            sl[j] = logits[(size_t)row0 * KC + j] * LOG2E;
        __syncthreads();
#pragma unroll
        for (int s = 0; s < NQ; s++) {
            const int r = threadIdx.x + s * TPB;
            if (r < nrows) contrib += row_compute(r);
        }
    }

    // ---- block reduction ----
    contrib = warp_reduce(contrib);
    if ((threadIdx.x & 31) == 0) ws[threadIdx.x >> 5] = contrib;
    __syncthreads();
    if (threadIdx.x < 32) {
        float v = (threadIdx.x < TPB / 32) ? ws[threadIdx.x] : 0.0f;
        v = warp_reduce(v);
        if (threadIdx.x == 0) {
            g_partials[blockIdx.x] = v;
            __threadfence();
            unsigned int tk = atomicAdd(&g_counter, 1u);
            s_last = (tk == (unsigned int)(nblocks - 1));
        }
    }
    __syncthreads();

    // ---- last arriving block: deterministic fixed-order final sum ----
    if (s_last) {
        float v = 0.0f;
        for (int i = threadIdx.x; i < nblocks; i += TPB) v += g_partials[i];
        v = warp_reduce(v);
        if ((threadIdx.x & 31) == 0) ws[threadIdx.x >> 5] = v;
        __syncthreads();
        if (threadIdx.x < 32) {
            float tv = (threadIdx.x < TPB / 32) ? ws[threadIdx.x] : 0.0f;
            tv = warp_reduce(tv);
            if (threadIdx.x == 0) {
                out[0] = tv / (float)B;
                g_counter = 0;               // re-arm for next graph replay
            }
        }
    }
}

extern "C" void kernel_launch(void* const* d_in, const int* in_sizes, int n_in,
                              void* d_out, int out_size) {
    const float* logits = (const float*)d_in[0];
    const int*   y      = (const int*)d_in[1];
    const int    B      = in_sizes[1];

    const int nblocks = (B + TILE - 1) / TILE;     // 4096 for B = 4,194,304

    ordinal_loss_fused<<<nblocks, TPB>>>(logits, y, (float*)d_out, B, nblocks);
}